// round 4
// baseline (speedup 1.0000x reference)
#include <cuda_runtime.h>
#include <math.h>

// Problem constants (fixed by the reference's setup_inputs)
#define NROWS   8192          // B
#define SLEN    4096          // S
#define NCHUNK  (SLEN / 32)   // 128 warp-iterations per row

#define DELTA_T 900.0
// COOLING_SIGN = -1.0

__device__ __forceinline__ double bounded_d(double raw, double lo, double hi) {
    double s = 1.0 / (1.0 + exp(-raw));
    return lo + (hi - lo) * s;
}

// One warp per batch row. The recurrence t' = a*t + b_s has constant a,
// so 32 steps are resolved per iteration with a warp prefix-sum:
//   t_{lane} = a^{lane} * ( a * t_carry + sum_{j<=lane} a^{-j} * b_j )
__global__ __launch_bounds__(256, 8)
void rc_scan_kernel(const float4* __restrict__ in,
                    const float*  __restrict__ pR,
                    const float*  __restrict__ pC,
                    const float*  __restrict__ pA,
                    const float*  __restrict__ pG,
                    float*        __restrict__ out)
{
    const int gwarp = (blockIdx.x * blockDim.x + threadIdx.x) >> 5;
    const int lane  = threadIdx.x & 31;
    if (gwarp >= NROWS) return;

    // --- scalar parameters (sigmoid-bounded), computed in double, negligible cost ---
    const double R = bounded_d((double)*pR, 1e-4, 0.2);
    const double C = bounded_d((double)*pC, 1e5, 1e8);
    const double A = bounded_d((double)*pA, 0.0, 0.2);
    const double G = bounded_d((double)*pG, 1.0, 20000.0);

    const double dtC = DELTA_T / C;
    const double a_d = 1.0 - dtC / R;       // ~0.9633 for given inputs
    const float  a   = (float)a_d;
    const float  kTo = (float)(dtC / R);    // coeff of t_out
    const float  kU  = (float)(-G * dtC);   // COOLING_SIGN * g * dt/C
    const float  kSo = (float)(A * dtC);    // coeff of solar

    const double la   = log(a_d);
    const float  apow = (float)exp(la * (double)lane);    // a^lane   (<=1)
    const float  ainv = (float)exp(-la * (double)lane);   // a^-lane  (<=~3.2)

    const float4* row  = in  + (size_t)gwarp * SLEN;  // 4 floats/step == one float4
    float*        orow = out + (size_t)gwarp * SLEN;

    // t_prev initial carry = t_in[b, 0] (channel 0 of step 0); broadcast load
    float t = __ldg((const float*)row);

    // software prefetch: load chunk 0 up front, then next-chunk during compute
    float4 v = row[lane];

    #pragma unroll 4
    for (int ch = 0; ch < NCHUNK; ch++) {
        float4 vn;
        if (ch + 1 < NCHUNK) vn = row[(ch + 1) * 32 + lane];

        // b_s = kTo*t_out + kU*u + kSo*solar ; rescale for the prefix
        float b = fmaf(kTo, v.y, fmaf(kU, v.z, kSo * v.w));
        float c = b * ainv;

        // inclusive warp prefix sum of c
        #pragma unroll
        for (int off = 1; off < 32; off <<= 1) {
            float n = __shfl_up_sync(0xffffffffu, c, off);
            if (lane >= off) c += n;
        }

        // t_lane = a^lane * (a * t_carry + prefix)
        float tv = apow * fmaf(a, t, c);
        orow[ch * 32 + lane] = tv;

        // carry out of this chunk = lane 31's value
        t = __shfl_sync(0xffffffffu, tv, 31);
        v = vn;
    }
}

extern "C" void kernel_launch(void* const* d_in, const int* in_sizes, int n_in,
                              void* d_out, int out_size)
{
    (void)in_sizes; (void)n_in; (void)out_size;
    const float4* in = (const float4*)d_in[0];
    const float*  rR = (const float*)d_in[1];
    const float*  rC = (const float*)d_in[2];
    const float*  rA = (const float*)d_in[3];
    const float*  rG = (const float*)d_in[4];
    float* out = (float*)d_out;

    // one warp per row: 8192 warps, 8 warps (256 threads) per block
    dim3 grid(NROWS / 8);
    dim3 block(256);
    rc_scan_kernel<<<grid, block>>>(in, rR, rC, rA, rG, out);
}

// round 7
// speedup vs baseline: 1.1177x; 1.1177x over previous
#include <cuda_runtime.h>
#include <math.h>

// Problem constants (fixed by the reference's setup_inputs)
#define NROWS   8192          // B
#define SLEN    4096          // S
#define NCHUNK  (SLEN / 32)   // 128 warp-iterations per row
#define PF      4             // prefetch depth (chunks in flight per warp)

#define DELTA_T 900.0
// COOLING_SIGN = -1.0

__device__ __forceinline__ double bounded_d(double raw, double lo, double hi) {
    double s = 1.0 / (1.0 + exp(-raw));
    return lo + (hi - lo) * s;
}

// One warp per batch row. The recurrence t' = a*t + b_s has constant a,
// so 32 steps are resolved per iteration with a warp prefix-sum:
//   t_{lane} = a^{lane} * ( a * t_carry + sum_{j<=lane} a^{-j} * b_j )
// Deep (4-chunk) software pipeline keeps 4 independent coalesced 512B
// warp-loads in flight to cover DRAM latency (the R4 binder).
// NOTE: no min-blocks occupancy hint — a (256,7) hint caps regs at 36 and
// would spill the float4 ring buffer to local memory, defeating the MLP fix.
__global__ __launch_bounds__(256)
void rc_scan_kernel(const float4* __restrict__ in,
                    const float*  __restrict__ pR,
                    const float*  __restrict__ pC,
                    const float*  __restrict__ pA,
                    const float*  __restrict__ pG,
                    float*        __restrict__ out)
{
    const int gwarp = (blockIdx.x * blockDim.x + threadIdx.x) >> 5;
    const int lane  = threadIdx.x & 31;
    if (gwarp >= NROWS) return;

    // --- scalar parameters (sigmoid-bounded), computed in double, negligible ---
    const double R = bounded_d((double)*pR, 1e-4, 0.2);
    const double C = bounded_d((double)*pC, 1e5, 1e8);
    const double A = bounded_d((double)*pA, 0.0, 0.2);
    const double G = bounded_d((double)*pG, 1.0, 20000.0);

    const double dtC = DELTA_T / C;
    const double a_d = 1.0 - dtC / R;       // ~0.9633 for given inputs
    const float  a   = (float)a_d;
    const float  kTo = (float)(dtC / R);    // coeff of t_out
    const float  kU  = (float)(-G * dtC);   // COOLING_SIGN * g * dt/C
    const float  kSo = (float)(A * dtC);    // coeff of solar

    const double la   = log(a_d);
    const float  apow = (float)exp(la * (double)lane);    // a^lane   (<=1)
    const float  ainv = (float)exp(-la * (double)lane);   // a^-lane  (<=~3.2)

    const float4* row  = in  + (size_t)gwarp * SLEN;  // 4 floats/step == one float4
    float*        orow = out + (size_t)gwarp * SLEN;

    // t_prev initial carry = t_in[b, 0] (channel 0 of step 0); broadcast load
    float t = __ldg((const float*)row);

    // Prime the 4-deep ring buffer: 4 independent coalesced loads in flight.
    float4 v[PF];
    #pragma unroll
    for (int k = 0; k < PF; k++)
        v[k] = row[k * 32 + lane];

    #pragma unroll 4
    for (int ch = 0; ch < NCHUNK; ch++) {
        // consume the oldest buffered chunk
        const float4 cur = v[ch & (PF - 1)];

        // refill that slot with chunk ch+PF (issued before the shfl chain,
        // so it overlaps the serial prefix + next 3 iterations)
        if (ch + PF < NCHUNK)
            v[ch & (PF - 1)] = row[(ch + PF) * 32 + lane];

        // b_s = kTo*t_out + kU*u + kSo*solar ; rescale for the prefix
        float b = fmaf(kTo, cur.y, fmaf(kU, cur.z, kSo * cur.w));
        float c = b * ainv;

        // inclusive warp prefix sum of c
        #pragma unroll
        for (int off = 1; off < 32; off <<= 1) {
            float n = __shfl_up_sync(0xffffffffu, c, off);
            if (lane >= off) c += n;
        }

        // t_lane = a^lane * (a * t_carry + prefix)
        float tv = apow * fmaf(a, t, c);
        orow[ch * 32 + lane] = tv;

        // carry out of this chunk = lane 31's value
        t = __shfl_sync(0xffffffffu, tv, 31);
    }
}

extern "C" void kernel_launch(void* const* d_in, const int* in_sizes, int n_in,
                              void* d_out, int out_size)
{
    (void)in_sizes; (void)n_in; (void)out_size;
    const float4* in = (const float4*)d_in[0];
    const float*  rR = (const float*)d_in[1];
    const float*  rC = (const float*)d_in[2];
    const float*  rA = (const float*)d_in[3];
    const float*  rG = (const float*)d_in[4];
    float* out = (float*)d_out;

    // one warp per row: 8192 warps, 8 warps (256 threads) per block
    dim3 grid(NROWS / 8);
    dim3 block(256);
    rc_scan_kernel<<<grid, block>>>(in, rR, rC, rA, rG, out);
}